// round 3
// baseline (speedup 1.0000x reference)
#include <cuda_runtime.h>

#define BATCH 16384
#define EMBED 300
#define NCTX  10
#define NNEG  20
#define NF4   75           // 300 floats = 75 float4 per row
#define WARPS_PER_BLOCK 8
#define BLOCK_THREADS   (WARPS_PER_BLOCK * 32)
#define GRID_BLOCKS     (BATCH / WARPS_PER_BLOCK)   // 2048

// intermediate: context-mean embeddings [BATCH, 300] (19.66 MB, static — no allocs)
__device__ float4 g_cm[BATCH * NF4];

// fused-reduction state (zero-init .bss; last block resets for graph replays)
__device__ float        g_sum;
__device__ unsigned int g_arrived;

__device__ __forceinline__ float log_sigmoid(float x) {
    return fminf(x, 0.0f) - log1pf(__expf(-fabsf(x)));
}

__device__ __forceinline__ float dot4(float4 a, float4 b) {
    return a.x * b.x + a.y * b.y + a.z * b.z + a.w * b.w;
}

// ───────────────────────── Phase A: ctx_w gathers only ─────────────────────
__global__ __launch_bounds__(BLOCK_THREADS)
void cbow_ctx_mean_kernel(const int*   __restrict__ context,  // [B, NCTX]
                          const float* __restrict__ ctx_w)    // [V, 300]
{
    const int warp = threadIdx.x >> 5;
    const int lane = threadIdx.x & 31;
    const int b    = blockIdx.x * WARPS_PER_BLOCK + warp;

    int idx = 0;
    if (lane < NCTX) idx = context[b * NCTX + lane];

    float4 cm0 = make_float4(0.f, 0.f, 0.f, 0.f);
    float4 cm1 = cm0;
    float4 cm2 = cm0;
    const bool tail = (lane < NF4 - 64);   // lane < 11

    #pragma unroll
    for (int c = 0; c < NCTX; ++c) {
        int row = __shfl_sync(0xffffffffu, idx, c);
        const float4* r = reinterpret_cast<const float4*>(ctx_w + (size_t)row * EMBED);
        float4 a0 = __ldg(r + lane);
        float4 a1 = __ldg(r + lane + 32);
        cm0.x += a0.x; cm0.y += a0.y; cm0.z += a0.z; cm0.w += a0.w;
        cm1.x += a1.x; cm1.y += a1.y; cm1.z += a1.z; cm1.w += a1.w;
        if (tail) {
            float4 a2 = __ldg(r + lane + 64);
            cm2.x += a2.x; cm2.y += a2.y; cm2.z += a2.z; cm2.w += a2.w;
        }
    }
    const float inv_c = 1.0f / (float)NCTX;
    cm0.x *= inv_c; cm0.y *= inv_c; cm0.z *= inv_c; cm0.w *= inv_c;
    cm1.x *= inv_c; cm1.y *= inv_c; cm1.z *= inv_c; cm1.w *= inv_c;
    cm2.x *= inv_c; cm2.y *= inv_c; cm2.z *= inv_c; cm2.w *= inv_c;

    float4* dst = g_cm + (size_t)b * NF4;
    dst[lane]      = cm0;
    dst[lane + 32] = cm1;
    if (tail) dst[lane + 64] = cm2;
}

// ───────────────────────── Phase B: cen_w gathers only ─────────────────────
__global__ __launch_bounds__(BLOCK_THREADS)
void cbow_score_kernel(const int*   __restrict__ center,     // [B]
                       const int*   __restrict__ negatives,  // [B, NNEG]
                       const float* __restrict__ cen_w,      // [V, 300]
                       float*       __restrict__ out)
{
    const int warp = threadIdx.x >> 5;
    const int lane = threadIdx.x & 31;
    const int b    = blockIdx.x * WARPS_PER_BLOCK + warp;

    // 21 indices: lane 0 = center, lanes 1..20 = negatives
    int idx = 0;
    if (lane == 0)                idx = center[b];
    else if (lane <= NNEG)        idx = negatives[b * NNEG + (lane - 1)];

    // load context mean
    const float4* src = g_cm + (size_t)b * NF4;
    const bool tail = (lane < NF4 - 64);
    float4 cm0 = src[lane];
    float4 cm1 = src[lane + 32];
    float4 cm2 = tail ? src[lane + 64] : make_float4(0.f, 0.f, 0.f, 0.f);

    float loss = 0.0f;
    #pragma unroll
    for (int t = 0; t < 1 + NNEG; ++t) {
        int row = __shfl_sync(0xffffffffu, idx, t);
        const float4* r = reinterpret_cast<const float4*>(cen_w + (size_t)row * EMBED);
        float4 a0 = __ldg(r + lane);
        float4 a1 = __ldg(r + lane + 32);
        float s = dot4(a0, cm0) + dot4(a1, cm1);
        if (tail) {
            float4 a2 = __ldg(r + lane + 64);
            s += dot4(a2, cm2);
        }
        #pragma unroll
        for (int off = 16; off > 0; off >>= 1)
            s += __shfl_xor_sync(0xffffffffu, s, off);
        loss += log_sigmoid(t == 0 ? s : -s);
    }

    __shared__ float sdata[WARPS_PER_BLOCK];
    if (lane == 0) sdata[warp] = -loss;
    __syncthreads();

    if (threadIdx.x == 0) {
        float tot = 0.f;
        #pragma unroll
        for (int i = 0; i < WARPS_PER_BLOCK; ++i) tot += sdata[i];

        atomicAdd(&g_sum, tot);
        __threadfence();
        unsigned prev = atomicAdd(&g_arrived, 1u);
        if (prev == GRID_BLOCKS - 1) {
            float total = g_sum;
            out[0] = total / (float)BATCH;
            g_sum = 0.0f;
            __threadfence();
            g_arrived = 0u;
        }
    }
}

extern "C" void kernel_launch(void* const* d_in, const int* in_sizes, int n_in,
                              void* d_out, int out_size)
{
    const int*   context   = (const int*)  d_in[0];
    const int*   center    = (const int*)  d_in[1];
    const int*   negatives = (const int*)  d_in[2];
    const float* ctx_w     = (const float*)d_in[3];
    const float* cen_w     = (const float*)d_in[4];
    float*       out       = (float*)d_out;

    cbow_ctx_mean_kernel<<<GRID_BLOCKS, BLOCK_THREADS>>>(context, ctx_w);
    cbow_score_kernel<<<GRID_BLOCKS, BLOCK_THREADS>>>(center, negatives, cen_w, out);
}